// round 1
// baseline (speedup 1.0000x reference)
#include <cuda_runtime.h>
#include <math.h>
#include <stdint.h>

// ---------------- problem constants ----------------
#define BB    32
#define HH    56
#define CC    384
#define LL    (HH*HH)           // 3136
#define NTOK  (BB*LL)           // 100352
#define NHEAD 12
#define HDIM  32
#define HID   1536
#define N3    1152              // 3*C
#define WN    49                // window tokens

// ---------------- scratch (device globals; allocation-free) ----------------
__device__ __align__(256) float g_ywin[(size_t)NTOK * CC];   // LN1 out (window order) / LN2 out
__device__ __align__(256) float g_big [(size_t)NTOK * HID];  // qkv (stride 1152) then hid (stride 1536)
__device__ __align__(256) float g_attn[(size_t)NTOK * CC];   // attention out (window order)
__device__ __align__(256) float g_xres[(size_t)NTOK * CC];   // x + proj (seq order)

// window-order row r -> sequence index (b*3136 + h*56 + w) with the +3 roll applied.
// Used both as gather source (LN1) and scatter destination (proj epilogue): the
// forward roll(-3) source and reverse roll(+3) destination are the same map.
__device__ __forceinline__ int win_to_seq(int r) {
    int n  = r % WN;
    int t  = r / WN;
    int wc = t & 7;
    int wr = (t >> 3) & 7;
    int b  = t >> 6;
    int n7 = n / 7;
    int h  = wr * 7 + n7;
    int w  = wc * 7 + (n - n7 * 7);
    int dh = h + 3; if (dh >= HH) dh -= HH;
    int dw = w + 3; if (dw >= HH) dw -= HH;
    return (b * HH + dh) * HH + dw;
}

// ---------------- LayerNorm (one warp per token) ----------------
template<bool PERM>
__global__ void ln_kernel(const float* __restrict__ X, const float* __restrict__ G,
                          const float* __restrict__ Bv, float* __restrict__ Y)
{
    int gw   = (blockIdx.x * blockDim.x + threadIdx.x) >> 5;
    int lane = threadIdx.x & 31;
    if (gw >= NTOK) return;
    int src = PERM ? win_to_seq(gw) : gw;
    const float4* xr = (const float4*)(X + (size_t)src * CC);
    float4 a = xr[lane], b = xr[32 + lane], c = xr[64 + lane];
    float s = a.x+a.y+a.z+a.w + b.x+b.y+b.z+b.w + c.x+c.y+c.z+c.w;
    float q = a.x*a.x+a.y*a.y+a.z*a.z+a.w*a.w
            + b.x*b.x+b.y*b.y+b.z*b.z+b.w*b.w
            + c.x*c.x+c.y*c.y+c.z*c.z+c.w*c.w;
    #pragma unroll
    for (int o = 16; o; o >>= 1) {
        s += __shfl_xor_sync(0xffffffffu, s, o);
        q += __shfl_xor_sync(0xffffffffu, q, o);
    }
    float mu  = s * (1.0f / CC);
    float var = q * (1.0f / CC) - mu * mu;
    float rs  = rsqrtf(var + 1e-5f);
    const float4* gg = (const float4*)G;
    const float4* bb = (const float4*)Bv;
    float4 g0 = gg[lane], g1 = gg[32+lane], g2 = gg[64+lane];
    float4 p0 = bb[lane], p1 = bb[32+lane], p2 = bb[64+lane];
    a.x=(a.x-mu)*rs*g0.x+p0.x; a.y=(a.y-mu)*rs*g0.y+p0.y; a.z=(a.z-mu)*rs*g0.z+p0.z; a.w=(a.w-mu)*rs*g0.w+p0.w;
    b.x=(b.x-mu)*rs*g1.x+p1.x; b.y=(b.y-mu)*rs*g1.y+p1.y; b.z=(b.z-mu)*rs*g1.z+p1.z; b.w=(b.w-mu)*rs*g1.w+p1.w;
    c.x=(c.x-mu)*rs*g2.x+p2.x; c.y=(c.y-mu)*rs*g2.y+p2.y; c.z=(c.z-mu)*rs*g2.z+p2.z; c.w=(c.w-mu)*rs*g2.w+p2.w;
    float4* yr = (float4*)(Y + (size_t)gw * CC);
    yr[lane] = a; yr[32 + lane] = b; yr[64 + lane] = c;
}

// ---------------- fp32 GEMM: C[M,N] = A[M,K] @ B[K,N] + bias, epilogue variants ----------------
// EPI 0: plain store
// EPI 1: exact GELU
// EPI 2: scatter row via win_to_seq + residual (resid in seq order)   [proj]
// EPI 3: add resid (same row order)                                   [fc2]
template<int EPI>
__global__ __launch_bounds__(256)
void gemm128(const float* __restrict__ A, const float* __restrict__ Bm,
             const float* __restrict__ bias, float* __restrict__ Cc,
             const float* __restrict__ resid, int K, int Nn)
{
    __shared__ float As[16][128];
    __shared__ float Bs[16][128];
    int tid = threadIdx.x;
    int ty8 = (tid >> 4) * 8;
    int tx8 = (tid & 15) * 8;
    const float* Ab = A  + (size_t)blockIdx.y * 128 * K;
    const float* Bb = Bm + (size_t)blockIdx.x * 128;
    float acc[8][8];
    #pragma unroll
    for (int i = 0; i < 8; i++)
        #pragma unroll
        for (int j = 0; j < 8; j++) acc[i][j] = 0.0f;

    for (int k0 = 0; k0 < K; k0 += 16) {
        #pragma unroll
        for (int t = 0; t < 2; t++) {
            int i  = tid + t * 256;
            int r  = i >> 2;
            int c4 = (i & 3) * 4;
            float4 va = *(const float4*)(Ab + (size_t)r * K + k0 + c4);
            As[c4+0][r] = va.x; As[c4+1][r] = va.y; As[c4+2][r] = va.z; As[c4+3][r] = va.w;
            int rb = i >> 5;
            int cb = (i & 31) * 4;
            float4 vb = *(const float4*)(Bb + (size_t)(k0 + rb) * Nn + cb);
            *(float4*)&Bs[rb][cb] = vb;
        }
        __syncthreads();
        #pragma unroll
        for (int kk = 0; kk < 16; kk++) {
            float ra[8], rb[8];
            #pragma unroll
            for (int i = 0; i < 8; i++) ra[i] = As[kk][ty8 + i];
            #pragma unroll
            for (int j = 0; j < 8; j++) rb[j] = Bs[kk][tx8 + j];
            #pragma unroll
            for (int i = 0; i < 8; i++)
                #pragma unroll
                for (int j = 0; j < 8; j++) acc[i][j] += ra[i] * rb[j];
        }
        __syncthreads();
    }

    int row0 = blockIdx.y * 128 + ty8;
    int col0 = blockIdx.x * 128 + tx8;
    float bv[8];
    #pragma unroll
    for (int j = 0; j < 8; j++) bv[j] = bias[col0 + j];
    #pragma unroll
    for (int i = 0; i < 8; i++) {
        int r = row0 + i;
        size_t orow;
        if (EPI == 2) orow = (size_t)win_to_seq(r) * Nn;
        else          orow = (size_t)r * Nn;
        float tmp[8];
        #pragma unroll
        for (int j = 0; j < 8; j++) {
            float v = acc[i][j] + bv[j];
            if (EPI == 1) v = 0.5f * v * (1.0f + erff(v * 0.7071067811865475f));
            if (EPI == 2 || EPI == 3) v += resid[orow + col0 + j];
            tmp[j] = v;
        }
        float4* cp = (float4*)(Cc + orow + col0);
        cp[0] = make_float4(tmp[0], tmp[1], tmp[2], tmp[3]);
        cp[1] = make_float4(tmp[4], tmp[5], tmp[6], tmp[7]);
    }
}

// ---------------- windowed attention: one block per (window, head) ----------------
__global__ __launch_bounds__(256)
void attn_kernel(const float* __restrict__ qkv, float* __restrict__ O)
{
    __shared__ float q[WN][33], k[WN][33], v[WN][33];
    __shared__ float s[WN][WN];
    int win = blockIdx.x, head = blockIdx.y;
    int tid = threadIdx.x;
    const float* base = qkv + (size_t)win * WN * N3 + head * HDIM;
    for (int i = tid; i < WN * HDIM; i += 256) {
        int n = i >> 5, d = i & 31;
        size_t ro = (size_t)n * N3 + d;
        q[n][d] = base[ro];
        k[n][d] = base[ro + CC];
        v[n][d] = base[ro + 2 * CC];
    }
    __syncthreads();
    for (int i = tid; i < WN * WN; i += 256) {
        int n = i / WN, m = i - n * WN;
        float a = 0.0f;
        #pragma unroll
        for (int d = 0; d < HDIM; d++) a += q[n][d] * k[m][d];
        s[n][m] = a * 0.17677669529663687f;   // 1/sqrt(32)
    }
    __syncthreads();
    if (tid < WN) {
        float mx = -1e30f;
        #pragma unroll 7
        for (int m = 0; m < WN; m++) mx = fmaxf(mx, s[tid][m]);
        float sum = 0.0f;
        #pragma unroll 7
        for (int m = 0; m < WN; m++) { float e = __expf(s[tid][m] - mx); s[tid][m] = e; sum += e; }
        float inv = 1.0f / sum;
        #pragma unroll 7
        for (int m = 0; m < WN; m++) s[tid][m] *= inv;
    }
    __syncthreads();
    for (int i = tid; i < WN * HDIM; i += 256) {
        int n = i >> 5, d = i & 31;
        float a = 0.0f;
        #pragma unroll
        for (int m = 0; m < WN; m++) a += s[n][m] * v[m][d];
        O[((size_t)win * WN + n) * CC + head * HDIM + d] = a;
    }
}

// ---------------- launcher ----------------
extern "C" void kernel_launch(void* const* d_in, const int* in_sizes, int n_in,
                              void* d_out, int out_size)
{
    const float* x      = (const float*)d_in[0];
    const float* ln1_g  = (const float*)d_in[1];
    const float* ln1_b  = (const float*)d_in[2];
    const float* w_qkv  = (const float*)d_in[3];
    const float* b_qkv  = (const float*)d_in[4];
    const float* w_proj = (const float*)d_in[5];
    const float* b_proj = (const float*)d_in[6];
    const float* ln2_g  = (const float*)d_in[7];
    const float* ln2_b  = (const float*)d_in[8];
    const float* w_fc1  = (const float*)d_in[9];
    const float* b_fc1  = (const float*)d_in[10];
    const float* w_fc2  = (const float*)d_in[11];
    const float* b_fc2  = (const float*)d_in[12];
    float* out = (float*)d_out;

    float *ywin, *big, *attn, *xres;
    cudaGetSymbolAddress((void**)&ywin, g_ywin);
    cudaGetSymbolAddress((void**)&big,  g_big);
    cudaGetSymbolAddress((void**)&attn, g_attn);
    cudaGetSymbolAddress((void**)&xres, g_xres);

    const int MT = NTOK / 128;   // 784 row tiles

    // 1) LN1 + roll + window partition
    ln_kernel<true><<<NTOK / 8, 256>>>(x, ln1_g, ln1_b, ywin);
    // 2) QKV GEMM: [100352,384] @ [384,1152]
    gemm128<0><<<dim3(N3 / 128, MT), 256>>>(ywin, w_qkv, b_qkv, big, nullptr, CC, N3);
    // 3) windowed attention
    attn_kernel<<<dim3(NTOK / WN, NHEAD), 256>>>(big, attn);
    // 4) proj GEMM + window reverse + roll back + residual
    gemm128<2><<<dim3(CC / 128, MT), 256>>>(attn, w_proj, b_proj, xres, x, CC, CC);
    // 5) LN2
    ln_kernel<false><<<NTOK / 8, 256>>>(xres, ln2_g, ln2_b, ywin);
    // 6) FC1 + exact GELU
    gemm128<1><<<dim3(HID / 128, MT), 256>>>(ywin, w_fc1, b_fc1, big, nullptr, CC, HID);
    // 7) FC2 + residual -> out
    gemm128<3><<<dim3(CC / 128, MT), 256>>>(big, w_fc2, b_fc2, out, xres, HID, CC);
}

// round 3
// speedup vs baseline: 1.6312x; 1.6312x over previous
#include <cuda_runtime.h>
#include <cuda_bf16.h>
#include <math.h>
#include <stdint.h>

// ---------------- problem constants ----------------
#define HHs   56
#define CCk   384
#define NTOK  100352
#define HID   1536
#define WN    49
#define K3A   1152          // 3*384
#define K3H   4608          // 3*1536

// ---------------- scratch (device globals) ----------------
__device__ __align__(256) __nv_bfloat16 g_act3[(size_t)NTOK * K3A];  // LN1 / attn / LN2 out (A3 layout)
__device__ __align__(256) __nv_bfloat16 g_hid3[(size_t)NTOK * K3H];  // gelu out (A3 layout)
__device__ __align__(256) float         g_qkv [(size_t)NTOK * 1152]; // qkv fp32
__device__ __align__(256) float         g_xres[(size_t)NTOK * 384];  // x + proj
__device__ __align__(256) __nv_bfloat16 g_wq3[1152 * K3A];
__device__ __align__(256) __nv_bfloat16 g_wp3[ 384 * K3A];
__device__ __align__(256) __nv_bfloat16 g_w13[1536 * K3A];
__device__ __align__(256) __nv_bfloat16 g_w23[ 384 * K3H];

// ---------------- PTX helpers (all baseline sm_80+, safe on plain sm_103) ----------------
__device__ __forceinline__ uint32_t smem_u32(const void* p) {
    uint32_t a;
    asm("{ .reg .u64 t; cvta.to.shared.u64 t, %1; cvt.u32.u64 %0, t; }" : "=r"(a) : "l"(p));
    return a;
}
#define CP_ASYNC16(dst, src) \
    asm volatile("cp.async.cg.shared.global [%0], [%1], 16;" :: "r"(dst), "l"(src))
#define CP_COMMIT() asm volatile("cp.async.commit_group;" ::: "memory")
#define CP_WAIT(n)  asm volatile("cp.async.wait_group %0;" :: "n"(n) : "memory")
#define LDSM_X4(r0, r1, r2, r3, addr) \
    asm volatile("ldmatrix.sync.aligned.m8n8.x4.shared.b16 {%0,%1,%2,%3}, [%4];" \
                 : "=r"(r0), "=r"(r1), "=r"(r2), "=r"(r3) : "r"(addr))

__device__ __forceinline__ void mma16816(float* c, const uint32_t* a, const uint32_t* b) {
    asm volatile("mma.sync.aligned.m16n8k16.row.col.f32.bf16.bf16.f32 "
        "{%0,%1,%2,%3}, {%4,%5,%6,%7}, {%8,%9}, {%0,%1,%2,%3};"
        : "+f"(c[0]), "+f"(c[1]), "+f"(c[2]), "+f"(c[3])
        : "r"(a[0]), "r"(a[1]), "r"(a[2]), "r"(a[3]), "r"(b[0]), "r"(b[1]));
}

// window-order row -> sequence row (roll map; same both directions)
__device__ __forceinline__ int win_to_seq(int r) {
    int n  = r % WN;
    int t  = r / WN;
    int wc = t & 7, wr = (t >> 3) & 7, b = t >> 6;
    int n7 = n / 7;
    int h = wr * 7 + n7, w = wc * 7 + (n - n7 * 7);
    int dh = h + 3; if (dh >= HHs) dh -= HHs;
    int dw = w + 3; if (dw >= HHs) dw -= HHs;
    return (b * HHs + dh) * HHs + dw;
}

// activation split store: A3 = [Ah | Al | Ah], pairs (k even)
__device__ __forceinline__ void act3_store2(__nv_bfloat16* base, int k, int Kd,
                                            float v0, float v1) {
    __nv_bfloat16 h0 = __float2bfloat16(v0), h1 = __float2bfloat16(v1);
    __nv_bfloat162 hp; hp.x = h0; hp.y = h1;
    __nv_bfloat162 lp;
    lp.x = __float2bfloat16(v0 - __bfloat162float(h0));
    lp.y = __float2bfloat16(v1 - __bfloat162float(h1));
    *(__nv_bfloat162*)(base + k)          = hp;
    *(__nv_bfloat162*)(base + 2 * Kd + k) = hp;
    *(__nv_bfloat162*)(base + Kd + k)     = lp;
}

// ---------------- weight prep: W[K][N] fp32 -> B3[N][3K] = [Bh | Bh | Bl] ----------------
__global__ void wprep3(const float* __restrict__ W, int K, int N, __nv_bfloat16* __restrict__ B3)
{
    __shared__ float t[32][33];
    int nb = blockIdx.x * 32, kb = blockIdx.y * 32;
    for (int i = threadIdx.y; i < 32; i += 8)
        t[i][threadIdx.x] = W[(size_t)(kb + i) * N + nb + threadIdx.x];
    __syncthreads();
    for (int i = threadIdx.y; i < 32; i += 8) {
        float v = t[threadIdx.x][i];                // = W[kb+tx][nb+i]
        __nv_bfloat16 h = __float2bfloat16(v);
        __nv_bfloat16 l = __float2bfloat16(v - __bfloat162float(h));
        size_t o = (size_t)(nb + i) * 3 * K + kb + threadIdx.x;
        B3[o] = h; B3[o + K] = h; B3[o + 2 * K] = l;
    }
}

// ---------------- LayerNorm -> A3 split bf16 (one warp per token) ----------------
template<bool PERM>
__global__ void ln_kernel(const float* __restrict__ X, const float* __restrict__ G,
                          const float* __restrict__ Bv, __nv_bfloat16* __restrict__ Y3)
{
    int gw   = (blockIdx.x * blockDim.x + threadIdx.x) >> 5;
    int lane = threadIdx.x & 31;
    if (gw >= NTOK) return;
    int src = PERM ? win_to_seq(gw) : gw;
    const float4* xr = (const float4*)(X + (size_t)src * CCk);
    float4 a = xr[lane], b = xr[32 + lane], c = xr[64 + lane];
    float s = a.x+a.y+a.z+a.w + b.x+b.y+b.z+b.w + c.x+c.y+c.z+c.w;
    float q = a.x*a.x+a.y*a.y+a.z*a.z+a.w*a.w
            + b.x*b.x+b.y*b.y+b.z*b.z+b.w*b.w
            + c.x*c.x+c.y*c.y+c.z*c.z+c.w*c.w;
    #pragma unroll
    for (int o = 16; o; o >>= 1) {
        s += __shfl_xor_sync(0xffffffffu, s, o);
        q += __shfl_xor_sync(0xffffffffu, q, o);
    }
    float mu  = s * (1.0f / CCk);
    float var = q * (1.0f / CCk) - mu * mu;
    float rs  = rsqrtf(var + 1e-5f);
    const float4* gg = (const float4*)G;
    const float4* bb = (const float4*)Bv;
    __nv_bfloat16* base = Y3 + (size_t)gw * K3A;
    #pragma unroll
    for (int seg = 0; seg < 3; seg++) {
        float4 v  = (seg == 0) ? a : (seg == 1) ? b : c;
        float4 g4 = gg[seg * 32 + lane];
        float4 b4 = bb[seg * 32 + lane];
        int k0 = seg * 128 + lane * 4;
        float w0 = (v.x - mu) * rs * g4.x + b4.x;
        float w1 = (v.y - mu) * rs * g4.y + b4.y;
        float w2 = (v.z - mu) * rs * g4.z + b4.z;
        float w3 = (v.w - mu) * rs * g4.w + b4.w;
        act3_store2(base, k0,     CCk, w0, w1);
        act3_store2(base, k0 + 2, CCk, w2, w3);
    }
}

// ---------------- attention: 1 thread per row, broadcast smem k/v ----------------
__global__ __launch_bounds__(64)
void attn_kernel(const float* __restrict__ qkv, __nv_bfloat16* __restrict__ O3)
{
    __shared__ float4 kk[WN * 8], vv[WN * 8];
    int win = blockIdx.x, head = blockIdx.y;
    int t = threadIdx.x;
    const float* base = qkv + (size_t)win * WN * 1152 + head * 32;
    for (int u = t; u < WN * 8; u += 64) {
        int m = u >> 3, j = u & 7;
        kk[u] = *(const float4*)(base + (size_t)m * 1152 + 384 + j * 4);
        vv[u] = *(const float4*)(base + (size_t)m * 1152 + 768 + j * 4);
    }
    __syncthreads();
    if (t >= WN) return;
    float q[32];
    const float4* qr = (const float4*)(base + (size_t)t * 1152);
    #pragma unroll
    for (int j = 0; j < 8; j++) {
        float4 f = qr[j];
        q[4*j] = f.x; q[4*j+1] = f.y; q[4*j+2] = f.z; q[4*j+3] = f.w;
    }
    float s[WN];
    #pragma unroll
    for (int m = 0; m < WN; m++) {
        float a = 0.0f;
        #pragma unroll
        for (int j = 0; j < 8; j++) {
            float4 f = kk[m*8 + j];
            a += q[4*j]*f.x + q[4*j+1]*f.y + q[4*j+2]*f.z + q[4*j+3]*f.w;
        }
        s[m] = a * 0.17677669529663687f;
    }
    float mx = -1e30f;
    #pragma unroll
    for (int m = 0; m < WN; m++) mx = fmaxf(mx, s[m]);
    float sum = 0.0f;
    #pragma unroll
    for (int m = 0; m < WN; m++) { s[m] = __expf(s[m] - mx); sum += s[m]; }
    float inv = 1.0f / sum;
    float o[32];
    #pragma unroll
    for (int j = 0; j < 32; j++) o[j] = 0.0f;
    #pragma unroll
    for (int m = 0; m < WN; m++) {
        float w = s[m] * inv;
        #pragma unroll
        for (int j = 0; j < 8; j++) {
            float4 f = vv[m*8 + j];
            o[4*j] += w*f.x; o[4*j+1] += w*f.y; o[4*j+2] += w*f.z; o[4*j+3] += w*f.w;
        }
    }
    __nv_bfloat16* ob = O3 + ((size_t)win * WN + t) * K3A;
    int k0 = head * 32;
    #pragma unroll
    for (int j = 0; j < 32; j += 2)
        act3_store2(ob, k0 + j, CCk, o[j], o[j + 1]);
}

// ---------------- bf16 mma.sync GEMM: 128x128 CTA, BK=64, 3-stage cp.async ----------------
#define STAGES 3
#define STAGE_BYTES 32768
#define SMEM_DYN 98304

__device__ __forceinline__ void load_stage(uint32_t sb, int tid,
    const __nv_bfloat16* __restrict__ A, const __nv_bfloat16* __restrict__ B,
    int m0, int n0, int K3, int k0, int slot)
{
    int r = tid >> 3, c = tid & 7;                 // 32 rows x 8 chunks per pass
    uint32_t sw = (uint32_t)((c ^ (r & 7)) << 4);
    uint32_t ab = sb + slot * STAGE_BYTES;
    uint32_t bb = ab + 16384;
    const __nv_bfloat16* ap = A + (size_t)(m0 + r) * K3 + k0 + c * 8;
    const __nv_bfloat16* bp = B + (size_t)(n0 + r) * K3 + k0 + c * 8;
    #pragma unroll
    for (int it = 0; it < 4; it++) {
        CP_ASYNC16(ab + (uint32_t)(r + it * 32) * 128 + sw, ap + (size_t)it * 32 * K3);
        CP_ASYNC16(bb + (uint32_t)(r + it * 32) * 128 + sw, bp + (size_t)it * 32 * K3);
    }
}

// EPI 0: qkv fp32   1: gelu -> A3 bf16 (hid3)   2: scatter+resid fp32   3: resid fp32
template<int EPI>
__global__ __launch_bounds__(256)
void gemm_mma(const __nv_bfloat16* __restrict__ A, const __nv_bfloat16* __restrict__ B,
              const float* __restrict__ bias, float* __restrict__ Co,
              __nv_bfloat16* __restrict__ O3, const float* __restrict__ resid,
              int K3, int Nn)
{
    extern __shared__ __align__(1024) char sm[];
    uint32_t sb = smem_u32(sm);
    int tid = threadIdx.x, lane = tid & 31, wid = tid >> 5;
    int wm = wid & 1, wn = wid >> 1;               // warp grid 2(m) x 4(n)
    int m0 = blockIdx.y * 128, n0 = blockIdx.x * 128;
    int KT = K3 >> 6;

    float acc[4][4][4];
    #pragma unroll
    for (int i = 0; i < 4; i++)
        #pragma unroll
        for (int j = 0; j < 4; j++)
            #pragma unroll
            for (int u = 0; u < 4; u++) acc[i][j][u] = 0.0f;

    load_stage(sb, tid, A, B, m0, n0, K3, 0, 0);  CP_COMMIT();
    load_stage(sb, tid, A, B, m0, n0, K3, 64, 1); CP_COMMIT();

    for (int kt = 0; kt < KT; kt++) {
        CP_WAIT(1);
        __syncthreads();
        if (kt + 2 < KT) load_stage(sb, tid, A, B, m0, n0, K3, (kt + 2) * 64, (kt + 2) % STAGES);
        CP_COMMIT();

        uint32_t As = sb + (kt % STAGES) * STAGE_BYTES;
        uint32_t Bs = As + 16384;
        #pragma unroll
        for (int kk = 0; kk < 4; kk++) {
            int ch = kk * 2 + (lane >> 4);
            uint32_t b[4][2];
            #pragma unroll
            for (int j2 = 0; j2 < 2; j2++) {
                int row = wn * 32 + j2 * 16 + (lane & 15);
                uint32_t addr = Bs + (uint32_t)row * 128 + (uint32_t)((ch ^ (row & 7)) << 4);
                uint32_t r0, r1, r2, r3;
                LDSM_X4(r0, r1, r2, r3, addr);
                b[2*j2][0] = r0; b[2*j2][1] = r2;
                b[2*j2+1][0] = r1; b[2*j2+1][1] = r3;
            }
            #pragma unroll
            for (int i = 0; i < 4; i++) {
                int row = wm * 64 + i * 16 + (lane & 15);
                uint32_t addr = As + (uint32_t)row * 128 + (uint32_t)((ch ^ (row & 7)) << 4);
                uint32_t a[4];
                LDSM_X4(a[0], a[1], a[2], a[3], addr);
                #pragma unroll
                for (int j = 0; j < 4; j++) mma16816(acc[i][j], a, b[j]);
            }
        }
    }
    CP_WAIT(0);
    __syncthreads();

    // stage C through smem (fp32, stride 132) for coalesced epilogue
    float* smf = (float*)sm;
    #pragma unroll
    for (int i = 0; i < 4; i++)
        #pragma unroll
        for (int j = 0; j < 4; j++) {
            int br = wm * 64 + i * 16 + (lane >> 2);
            int bc = wn * 32 + j * 8 + 2 * (lane & 3);
            *(float2*)&smf[br * 132 + bc]       = make_float2(acc[i][j][0], acc[i][j][1]);
            *(float2*)&smf[(br + 8) * 132 + bc] = make_float2(acc[i][j][2], acc[i][j][3]);
        }
    __syncthreads();

    int r   = tid >> 1;
    int cb0 = (tid & 1) * 64;
    int grow = m0 + r;
    const float* srow = &smf[r * 132 + cb0];
    if (EPI == 0) {
        float* dst = Co + (size_t)grow * Nn + n0 + cb0;
        #pragma unroll
        for (int c = 0; c < 64; c += 4) {
            float4 o;
            o.x = srow[c+0] + bias[n0+cb0+c+0];
            o.y = srow[c+1] + bias[n0+cb0+c+1];
            o.z = srow[c+2] + bias[n0+cb0+c+2];
            o.w = srow[c+3] + bias[n0+cb0+c+3];
            *(float4*)(dst + c) = o;
        }
    } else if (EPI == 1) {
        __nv_bfloat16* base = O3 + (size_t)grow * 3 * Nn;
        #pragma unroll
        for (int c = 0; c < 64; c += 2) {
            int gcol = n0 + cb0 + c;
            float v0 = srow[c]   + bias[gcol];
            float v1 = srow[c+1] + bias[gcol+1];
            v0 = 0.5f * v0 * (1.0f + erff(v0 * 0.70710678118654752f));
            v1 = 0.5f * v1 * (1.0f + erff(v1 * 0.70710678118654752f));
            act3_store2(base, gcol, Nn, v0, v1);
        }
    } else {
        size_t orow = (EPI == 2) ? (size_t)win_to_seq(grow) * Nn : (size_t)grow * Nn;
        float* dst = Co + orow + n0 + cb0;
        const float* rp = resid + orow + n0 + cb0;
        #pragma unroll
        for (int c = 0; c < 64; c += 4) {
            float4 rr = *(const float4*)(rp + c);
            float4 o;
            o.x = srow[c+0] + bias[n0+cb0+c+0] + rr.x;
            o.y = srow[c+1] + bias[n0+cb0+c+1] + rr.y;
            o.z = srow[c+2] + bias[n0+cb0+c+2] + rr.z;
            o.w = srow[c+3] + bias[n0+cb0+c+3] + rr.w;
            *(float4*)(dst + c) = o;
        }
    }
}

// ---------------- launcher ----------------
extern "C" void kernel_launch(void* const* d_in, const int* in_sizes, int n_in,
                              void* d_out, int out_size)
{
    const float* x      = (const float*)d_in[0];
    const float* ln1_g  = (const float*)d_in[1];
    const float* ln1_b  = (const float*)d_in[2];
    const float* w_qkv  = (const float*)d_in[3];
    const float* b_qkv  = (const float*)d_in[4];
    const float* w_proj = (const float*)d_in[5];
    const float* b_proj = (const float*)d_in[6];
    const float* ln2_g  = (const float*)d_in[7];
    const float* ln2_b  = (const float*)d_in[8];
    const float* w_fc1  = (const float*)d_in[9];
    const float* b_fc1  = (const float*)d_in[10];
    const float* w_fc2  = (const float*)d_in[11];
    const float* b_fc2  = (const float*)d_in[12];
    float* out = (float*)d_out;

    __nv_bfloat16 *act3, *hid3, *wq3, *wp3, *w13, *w23;
    float *qkv, *xres;
    cudaGetSymbolAddress((void**)&act3, g_act3);
    cudaGetSymbolAddress((void**)&hid3, g_hid3);
    cudaGetSymbolAddress((void**)&qkv,  g_qkv);
    cudaGetSymbolAddress((void**)&xres, g_xres);
    cudaGetSymbolAddress((void**)&wq3,  g_wq3);
    cudaGetSymbolAddress((void**)&wp3,  g_wp3);
    cudaGetSymbolAddress((void**)&w13,  g_w13);
    cudaGetSymbolAddress((void**)&w23,  g_w23);

    cudaFuncSetAttribute(gemm_mma<0>, cudaFuncAttributeMaxDynamicSharedMemorySize, SMEM_DYN);
    cudaFuncSetAttribute(gemm_mma<1>, cudaFuncAttributeMaxDynamicSharedMemorySize, SMEM_DYN);
    cudaFuncSetAttribute(gemm_mma<2>, cudaFuncAttributeMaxDynamicSharedMemorySize, SMEM_DYN);
    cudaFuncSetAttribute(gemm_mma<3>, cudaFuncAttributeMaxDynamicSharedMemorySize, SMEM_DYN);

    // weight prep
    wprep3<<<dim3(1152/32, 384/32),  dim3(32, 8)>>>(w_qkv,  384,  1152, wq3);
    wprep3<<<dim3( 384/32, 384/32),  dim3(32, 8)>>>(w_proj, 384,   384, wp3);
    wprep3<<<dim3(1536/32, 384/32),  dim3(32, 8)>>>(w_fc1,  384,  1536, w13);
    wprep3<<<dim3( 384/32, 1536/32), dim3(32, 8)>>>(w_fc2,  1536,  384, w23);

    const int MT = NTOK / 128;   // 784

    // 1) LN1 + roll + window partition -> A3
    ln_kernel<true><<<NTOK / 8, 256>>>(x, ln1_g, ln1_b, act3);
    // 2) QKV
    gemm_mma<0><<<dim3(1152/128, MT), 256, SMEM_DYN>>>(act3, wq3, b_qkv, qkv, nullptr, nullptr, K3A, 1152);
    // 3) attention -> A3
    attn_kernel<<<dim3(NTOK / WN, 12), 64>>>(qkv, act3);
    // 4) proj + reverse/roll + residual
    gemm_mma<2><<<dim3( 384/128, MT), 256, SMEM_DYN>>>(act3, wp3, b_proj, xres, nullptr, x, K3A, 384);
    // 5) LN2 -> A3
    ln_kernel<false><<<NTOK / 8, 256>>>(xres, ln2_g, ln2_b, act3);
    // 6) FC1 + GELU -> A3(hid)
    gemm_mma<1><<<dim3(1536/128, MT), 256, SMEM_DYN>>>(act3, w13, b_fc1, nullptr, hid3, nullptr, K3A, 1536);
    // 7) FC2 + residual -> out
    gemm_mma<3><<<dim3( 384/128, MT), 256, SMEM_DYN>>>(hid3, w23, b_fc2, out, nullptr, xres, K3H, 384);
}

// round 4
// speedup vs baseline: 2.0899x; 1.2812x over previous
#include <cuda_runtime.h>
#include <cuda_bf16.h>
#include <math.h>
#include <stdint.h>

// ---------------- problem constants ----------------
#define HHs   56
#define NTOK  100352
#define WN    49
#define NC_A  6      // K=384  -> 6 chunks of 64
#define NC_H  24     // K=1536 -> 24 chunks of 64

// ---------------- scratch: chunk-major, pre-swizzled layouts ----------------
// act: [12 chunks][NTOK][64 bf16]  (chunks 0..5 = hi, 6..11 = lo)
__device__ __align__(1024) __nv_bfloat16 g_act[(size_t)12 * NTOK * 64];
// hid: [48 chunks][NTOK][64]
__device__ __align__(1024) __nv_bfloat16 g_hid[(size_t)48 * NTOK * 64];
__device__ __align__(256) float g_qkv [(size_t)NTOK * 1152];
__device__ __align__(256) float g_xres[(size_t)NTOK * 384];
// weights: [2*NC chunks][N][64]
__device__ __align__(1024) __nv_bfloat16 g_wq[(size_t)12 * 1152 * 64];
__device__ __align__(1024) __nv_bfloat16 g_wp[(size_t)12 *  384 * 64];
__device__ __align__(1024) __nv_bfloat16 g_w1[(size_t)12 * 1536 * 64];
__device__ __align__(1024) __nv_bfloat16 g_w2[(size_t)48 *  384 * 64];

// ---------------- PTX helpers (sm_90 baseline; safe on plain sm_103) ----------------
__device__ __forceinline__ uint32_t smem_u32(const void* p) {
    uint32_t a;
    asm("{ .reg .u64 t; cvta.to.shared.u64 t, %1; cvt.u32.u64 %0, t; }" : "=r"(a) : "l"(p));
    return a;
}
#define MBARRIER_INIT(mb, c) \
    asm volatile("mbarrier.init.shared.b64 [%0], %1;" :: "r"((uint32_t)(mb)), "r"((uint32_t)(c)) : "memory")
#define MBARRIER_EXPECT_TX(mb, n) \
    asm volatile("mbarrier.arrive.expect_tx.shared.b64 _, [%0], %1;" :: "r"((uint32_t)(mb)), "r"((uint32_t)(n)) : "memory")
#define MBARRIER_WAIT_PARITY(mb, par) do { \
    uint32_t _m = (uint32_t)(mb), _p = (uint32_t)(par), _d; \
    asm volatile("{\n\t.reg .pred p;\n\t" \
        "mbarrier.try_wait.parity.acquire.cta.shared::cta.b64 p, [%1], %2;\n\t" \
        "selp.b32 %0, 1, 0, p;\n\t}" : "=r"(_d) : "r"(_m), "r"(_p) : "memory"); \
    if (!_d) { \
        asm volatile("{\n\t.reg .pred P1;\n\t" \
            "WL_%=:\n\t" \
            "mbarrier.try_wait.parity.acquire.cta.shared::cta.b64 P1, [%0], %1, 0x989680;\n\t" \
            "@P1 bra.uni WD_%=;\n\t" \
            "bra.uni WL_%=;\n\t" \
            "WD_%=:\n\t}" :: "r"(_m), "r"(_p) : "memory"); \
    } } while (0)
#define BULK_G2S(dst, src, n, mb) \
    asm volatile("cp.async.bulk.shared::cluster.global.mbarrier::complete_tx::bytes [%0], [%1], %2, [%3];" \
        :: "r"((uint32_t)(dst)), "l"(src), "r"((uint32_t)(n)), "r"((uint32_t)(mb)) : "memory")
#define FENCE_ASYNC() asm volatile("fence.proxy.async.shared::cta;" ::: "memory")
#define LDSM_X4(r0, r1, r2, r3, addr) \
    asm volatile("ldmatrix.sync.aligned.m8n8.x4.shared.b16 {%0,%1,%2,%3}, [%4];" \
                 : "=r"(r0), "=r"(r1), "=r"(r2), "=r"(r3) : "r"(addr))

__device__ __forceinline__ void mma16816(float* c, const uint32_t* a, const uint32_t* b) {
    asm volatile("mma.sync.aligned.m16n8k16.row.col.f32.bf16.bf16.f32 "
        "{%0,%1,%2,%3}, {%4,%5,%6,%7}, {%8,%9}, {%0,%1,%2,%3};"
        : "+f"(c[0]), "+f"(c[1]), "+f"(c[2]), "+f"(c[3])
        : "r"(a[0]), "r"(a[1]), "r"(a[2]), "r"(a[3]), "r"(b[0]), "r"(b[1]));
}

// window-order row -> sequence row (roll map; same both directions)
__device__ __forceinline__ int win_to_seq(int r) {
    int n  = r % WN;
    int t  = r / WN;
    int wc = t & 7, wr = (t >> 3) & 7, b = t >> 6;
    int n7 = n / 7;
    int h = wr * 7 + n7, w = wc * 7 + (n - n7 * 7);
    int dh = h + 3; if (dh >= HHs) dh -= HHs;
    int dw = w + 3; if (dw >= HHs) dw -= HHs;
    return (b * HHs + dh) * HHs + dw;
}

// split hi/lo store of 2 adjacent cols into chunk-major swizzled layout
// base: bf16*; nc = #hi chunks; rows = #rows in layout; tok = row; k even
__device__ __forceinline__ void split_store2(__nv_bfloat16* base, int nc, int rows,
                                             int tok, int k, float v0, float v1) {
    int ch  = k >> 6;
    int idx = ((((k >> 3) & 7) ^ (tok & 7)) << 3) + (k & 7);
    __nv_bfloat16 h0 = __float2bfloat16(v0), h1 = __float2bfloat16(v1);
    __nv_bfloat162 hp; hp.x = h0; hp.y = h1;
    __nv_bfloat162 lp;
    lp.x = __float2bfloat16(v0 - __bfloat162float(h0));
    lp.y = __float2bfloat16(v1 - __bfloat162float(h1));
    *(__nv_bfloat162*)(base + ((size_t)ch        * rows + tok) * 64 + idx) = hp;
    *(__nv_bfloat162*)(base + ((size_t)(nc + ch) * rows + tok) * 64 + idx) = lp;
}

// ---------------- weight prep: W[K][N] fp32 -> [2*NC][N][64] swizzled ----------------
__global__ void wprep(const float* __restrict__ W, int K, int N, __nv_bfloat16* __restrict__ O)
{
    __shared__ float t[32][33];
    int nb = blockIdx.x * 32, kb = blockIdx.y * 32;
    for (int i = threadIdx.y; i < 32; i += 8)
        t[i][threadIdx.x] = W[(size_t)(kb + i) * N + nb + threadIdx.x];
    __syncthreads();
    int NC = K >> 6;
    for (int i = threadIdx.y; i < 32; i += 8) {
        float v = t[threadIdx.x][i];            // = W[kb+tx][nb+i]
        int k = kb + threadIdx.x, n = nb + i;
        __nv_bfloat16 h = __float2bfloat16(v);
        __nv_bfloat16 l = __float2bfloat16(v - __bfloat162float(h));
        int ch  = k >> 6;
        int idx = ((((k >> 3) & 7) ^ (n & 7)) << 3) + (k & 7);
        O[((size_t)ch        * N + n) * 64 + idx] = h;
        O[((size_t)(NC + ch) * N + n) * 64 + idx] = l;
    }
}

// ---------------- LayerNorm -> split chunked bf16 (one warp per token) ----------------
template<bool PERM>
__global__ void ln_kernel(const float* __restrict__ X, const float* __restrict__ G,
                          const float* __restrict__ Bv, __nv_bfloat16* __restrict__ Y)
{
    int gw   = (blockIdx.x * blockDim.x + threadIdx.x) >> 5;
    int lane = threadIdx.x & 31;
    if (gw >= NTOK) return;
    int src = PERM ? win_to_seq(gw) : gw;
    const float4* xr = (const float4*)(X + (size_t)src * 384);
    float4 a = xr[lane], b = xr[32 + lane], c = xr[64 + lane];
    float s = a.x+a.y+a.z+a.w + b.x+b.y+b.z+b.w + c.x+c.y+c.z+c.w;
    float q = a.x*a.x+a.y*a.y+a.z*a.z+a.w*a.w
            + b.x*b.x+b.y*b.y+b.z*b.z+b.w*b.w
            + c.x*c.x+c.y*c.y+c.z*c.z+c.w*c.w;
    #pragma unroll
    for (int o = 16; o; o >>= 1) {
        s += __shfl_xor_sync(0xffffffffu, s, o);
        q += __shfl_xor_sync(0xffffffffu, q, o);
    }
    float mu  = s * (1.0f / 384.0f);
    float var = q * (1.0f / 384.0f) - mu * mu;
    float rs  = rsqrtf(var + 1e-5f);
    const float4* gg = (const float4*)G;
    const float4* bb = (const float4*)Bv;
    #pragma unroll
    for (int seg = 0; seg < 3; seg++) {
        float4 v  = (seg == 0) ? a : (seg == 1) ? b : c;
        float4 g4 = gg[seg * 32 + lane];
        float4 b4 = bb[seg * 32 + lane];
        int k0 = seg * 128 + lane * 4;
        float w0 = (v.x - mu) * rs * g4.x + b4.x;
        float w1 = (v.y - mu) * rs * g4.y + b4.y;
        float w2 = (v.z - mu) * rs * g4.z + b4.z;
        float w3 = (v.w - mu) * rs * g4.w + b4.w;
        split_store2(Y, NC_A, NTOK, gw, k0,     w0, w1);
        split_store2(Y, NC_A, NTOK, gw, k0 + 2, w2, w3);
    }
}

// ---------------- attention: 1 thread per row, broadcast smem k/v ----------------
__global__ __launch_bounds__(64)
void attn_kernel(const float* __restrict__ qkv, __nv_bfloat16* __restrict__ O)
{
    __shared__ float4 kk[WN * 8], vv[WN * 8];
    int win = blockIdx.x, head = blockIdx.y;
    int t = threadIdx.x;
    const float* base = qkv + (size_t)win * WN * 1152 + head * 32;
    for (int u = t; u < WN * 8; u += 64) {
        int m = u >> 3, j = u & 7;
        kk[u] = *(const float4*)(base + (size_t)m * 1152 + 384 + j * 4);
        vv[u] = *(const float4*)(base + (size_t)m * 1152 + 768 + j * 4);
    }
    __syncthreads();
    if (t >= WN) return;
    float q[32];
    const float4* qr = (const float4*)(base + (size_t)t * 1152);
    #pragma unroll
    for (int j = 0; j < 8; j++) {
        float4 f = qr[j];
        q[4*j] = f.x; q[4*j+1] = f.y; q[4*j+2] = f.z; q[4*j+3] = f.w;
    }
    float s[WN];
    #pragma unroll
    for (int m = 0; m < WN; m++) {
        float a = 0.0f;
        #pragma unroll
        for (int j = 0; j < 8; j++) {
            float4 f = kk[m*8 + j];
            a += q[4*j]*f.x + q[4*j+1]*f.y + q[4*j+2]*f.z + q[4*j+3]*f.w;
        }
        s[m] = a * 0.17677669529663687f;
    }
    float mx = -1e30f;
    #pragma unroll
    for (int m = 0; m < WN; m++) mx = fmaxf(mx, s[m]);
    float sum = 0.0f;
    #pragma unroll
    for (int m = 0; m < WN; m++) { s[m] = __expf(s[m] - mx); sum += s[m]; }
    float inv = 1.0f / sum;
    float o[32];
    #pragma unroll
    for (int j = 0; j < 32; j++) o[j] = 0.0f;
    #pragma unroll
    for (int m = 0; m < WN; m++) {
        float w = s[m] * inv;
        #pragma unroll
        for (int j = 0; j < 8; j++) {
            float4 f = vv[m*8 + j];
            o[4*j] += w*f.x; o[4*j+1] += w*f.y; o[4*j+2] += w*f.z; o[4*j+3] += w*f.w;
        }
    }
    int tok = win * WN + t;
    int k0 = head * 32;
    #pragma unroll
    for (int j = 0; j < 32; j += 2)
        split_store2(O, NC_A, NTOK, tok, k0 + j, o[j], o[j + 1]);
}

// ---------------- bf16x3 mma.sync GEMM, bulk-copy pipeline ----------------
// tiles: CTA 128(M) x 128(N), k-chunk 64, 3 stages of 32KB
#define STAGES 3
#define STG_BYTES 32768
#define MBAR_OFF 98304
#define SMEM_DYN (98304 + 64)

// EPI 0: qkv fp32   1: gelu -> chunked hid   2: scatter+resid fp32   3: resid fp32
template<int EPI>
__global__ __launch_bounds__(256)
void gemm_mma(const __nv_bfloat16* __restrict__ A, const __nv_bfloat16* __restrict__ B,
              const float* __restrict__ bias, float* __restrict__ Co,
              __nv_bfloat16* __restrict__ O2, const float* __restrict__ resid,
              int NC, int Nn)
{
    extern __shared__ __align__(1024) char sm[];
    uint32_t sb = smem_u32(sm);
    int tid = threadIdx.x, lane = tid & 31, wid = tid >> 5;
    int wm = wid & 1, wn = wid >> 1;
    int m0 = blockIdx.y * 128, n0 = blockIdx.x * 128;
    int NK = NC * 3;

    if (tid == 0) {
        MBARRIER_INIT(sb + MBAR_OFF,      1);
        MBARRIER_INIT(sb + MBAR_OFF + 8,  1);
        MBARRIER_INIT(sb + MBAR_OFF + 16, 1);
        FENCE_ASYNC();
    }
    __syncthreads();

    // stage issue helper (tid 0 only)
    auto issue = [&](int idx) {
        int j = idx / 3, t3 = idx - 3 * j;
        int ach = j + (t3 == 1 ? NC : 0);
        int bch = j + (t3 == 2 ? NC : 0);
        const char* asrc = (const char*)A + ((size_t)ach * NTOK + m0) * 128;
        const char* bsrc = (const char*)B + ((size_t)bch * Nn   + n0) * 128;
        int s = idx % STAGES;
        uint32_t dst = sb + s * STG_BYTES;
        uint32_t mb  = sb + MBAR_OFF + s * 8;
        MBARRIER_EXPECT_TX(mb, 32768);
        BULK_G2S(dst,         asrc, 16384, mb);
        BULK_G2S(dst + 16384, bsrc, 16384, mb);
    };
    if (tid == 0) { issue(0); issue(1); issue(2); }

    float acc[4][4][4];
    #pragma unroll
    for (int i = 0; i < 4; i++)
        #pragma unroll
        for (int j = 0; j < 4; j++)
            #pragma unroll
            for (int u = 0; u < 4; u++) acc[i][j][u] = 0.0f;

    for (int i = 0; i < NK; i++) {
        int s = i % STAGES;
        MBARRIER_WAIT_PARITY(sb + MBAR_OFF + s * 8, (i / STAGES) & 1);

        uint32_t As = sb + s * STG_BYTES;
        uint32_t Bs = As + 16384;
        #pragma unroll
        for (int kk = 0; kk < 4; kk++) {
            int ch = kk * 2 + (lane >> 4);
            uint32_t b[4][2];
            #pragma unroll
            for (int j2 = 0; j2 < 2; j2++) {
                int row = wn * 32 + j2 * 16 + (lane & 15);
                uint32_t addr = Bs + (uint32_t)row * 128 + (uint32_t)((ch ^ (row & 7)) << 4);
                uint32_t r0, r1, r2, r3;
                LDSM_X4(r0, r1, r2, r3, addr);
                b[2*j2][0] = r0; b[2*j2][1] = r2;
                b[2*j2+1][0] = r1; b[2*j2+1][1] = r3;
            }
            #pragma unroll
            for (int ii = 0; ii < 4; ii++) {
                int row = wm * 64 + ii * 16 + (lane & 15);
                uint32_t addr = As + (uint32_t)row * 128 + (uint32_t)((ch ^ (row & 7)) << 4);
                uint32_t a[4];
                LDSM_X4(a[0], a[1], a[2], a[3], addr);
                #pragma unroll
                for (int j = 0; j < 4; j++) mma16816(acc[ii][j], a, b[j]);
            }
        }
        __syncthreads();                    // slot s fully consumed
        if (tid == 0 && i + STAGES < NK) issue(i + STAGES);
    }

    // stage C through smem (fp32, stride 132) for coalesced epilogue
    float* smf = (float*)sm;
    #pragma unroll
    for (int i = 0; i < 4; i++)
        #pragma unroll
        for (int j = 0; j < 4; j++) {
            int br = wm * 64 + i * 16 + (lane >> 2);
            int bc = wn * 32 + j * 8 + 2 * (lane & 3);
            *(float2*)&smf[br * 132 + bc]       = make_float2(acc[i][j][0], acc[i][j][1]);
            *(float2*)&smf[(br + 8) * 132 + bc] = make_float2(acc[i][j][2], acc[i][j][3]);
        }
    __syncthreads();

    int r    = tid >> 1;
    int cb0  = (tid & 1) * 64;
    int grow = m0 + r;
    const float* srow = &smf[r * 132 + cb0];
    if (EPI == 0) {
        float* dst = Co + (size_t)grow * Nn + n0 + cb0;
        #pragma unroll
        for (int c = 0; c < 64; c += 4) {
            float4 o;
            o.x = srow[c+0] + bias[n0+cb0+c+0];
            o.y = srow[c+1] + bias[n0+cb0+c+1];
            o.z = srow[c+2] + bias[n0+cb0+c+2];
            o.w = srow[c+3] + bias[n0+cb0+c+3];
            *(float4*)(dst + c) = o;
        }
    } else if (EPI == 1) {
        int gc0   = n0 + cb0;               // multiple of 64
        int ch    = gc0 >> 6;
        int ncout = Nn >> 6;
        __nv_bfloat16* hi = O2 + ((size_t)ch          * NTOK + grow) * 64;
        __nv_bfloat16* lo = O2 + ((size_t)(ncout + ch)* NTOK + grow) * 64;
        #pragma unroll
        for (int c = 0; c < 64; c += 2) {
            float v0 = srow[c]   + bias[gc0 + c];
            float v1 = srow[c+1] + bias[gc0 + c + 1];
            v0 = 0.5f * v0 * (1.0f + erff(v0 * 0.70710678118654752f));
            v1 = 0.5f * v1 * (1.0f + erff(v1 * 0.70710678118654752f));
            int idx = ((((c >> 3) & 7) ^ (grow & 7)) << 3) + (c & 7);
            __nv_bfloat16 h0 = __float2bfloat16(v0), h1 = __float2bfloat16(v1);
            __nv_bfloat162 hp; hp.x = h0; hp.y = h1;
            __nv_bfloat162 lp;
            lp.x = __float2bfloat16(v0 - __bfloat162float(h0));
            lp.y = __float2bfloat16(v1 - __bfloat162float(h1));
            *(__nv_bfloat162*)(hi + idx) = hp;
            *(__nv_bfloat162*)(lo + idx) = lp;
        }
    } else {
        size_t orow = (EPI == 2) ? (size_t)win_to_seq(grow) * Nn : (size_t)grow * Nn;
        float* dst = Co + orow + n0 + cb0;
        const float* rp = resid + orow + n0 + cb0;
        #pragma unroll
        for (int c = 0; c < 64; c += 4) {
            float4 rr = *(const float4*)(rp + c);
            float4 o;
            o.x = srow[c+0] + bias[n0+cb0+c+0] + rr.x;
            o.y = srow[c+1] + bias[n0+cb0+c+1] + rr.y;
            o.z = srow[c+2] + bias[n0+cb0+c+2] + rr.z;
            o.w = srow[c+3] + bias[n0+cb0+c+3] + rr.w;
            *(float4*)(dst + c) = o;
        }
    }
}

// ---------------- launcher ----------------
extern "C" void kernel_launch(void* const* d_in, const int* in_sizes, int n_in,
                              void* d_out, int out_size)
{
    const float* x      = (const float*)d_in[0];
    const float* ln1_g  = (const float*)d_in[1];
    const float* ln1_b  = (const float*)d_in[2];
    const float* w_qkv  = (const float*)d_in[3];
    const float* b_qkv  = (const float*)d_in[4];
    const float* w_proj = (const float*)d_in[5];
    const float* b_proj = (const float*)d_in[6];
    const float* ln2_g  = (const float*)d_in[7];
    const float* ln2_b  = (const float*)d_in[8];
    const float* w_fc1  = (const float*)d_in[9];
    const float* b_fc1  = (const float*)d_in[10];
    const float* w_fc2  = (const float*)d_in[11];
    const float* b_fc2  = (const float*)d_in[12];
    float* out = (float*)d_out;

    __nv_bfloat16 *act, *hid, *wq, *wp, *w1, *w2;
    float *qkv, *xres;
    cudaGetSymbolAddress((void**)&act,  g_act);
    cudaGetSymbolAddress((void**)&hid,  g_hid);
    cudaGetSymbolAddress((void**)&qkv,  g_qkv);
    cudaGetSymbolAddress((void**)&xres, g_xres);
    cudaGetSymbolAddress((void**)&wq,   g_wq);
    cudaGetSymbolAddress((void**)&wp,   g_wp);
    cudaGetSymbolAddress((void**)&w1,   g_w1);
    cudaGetSymbolAddress((void**)&w2,   g_w2);

    cudaFuncSetAttribute(gemm_mma<0>, cudaFuncAttributeMaxDynamicSharedMemorySize, SMEM_DYN);
    cudaFuncSetAttribute(gemm_mma<1>, cudaFuncAttributeMaxDynamicSharedMemorySize, SMEM_DYN);
    cudaFuncSetAttribute(gemm_mma<2>, cudaFuncAttributeMaxDynamicSharedMemorySize, SMEM_DYN);
    cudaFuncSetAttribute(gemm_mma<3>, cudaFuncAttributeMaxDynamicSharedMemorySize, SMEM_DYN);

    // weight prep
    wprep<<<dim3(1152/32,  384/32), dim3(32, 8)>>>(w_qkv,  384,  1152, wq);
    wprep<<<dim3( 384/32,  384/32), dim3(32, 8)>>>(w_proj, 384,   384, wp);
    wprep<<<dim3(1536/32,  384/32), dim3(32, 8)>>>(w_fc1,  384,  1536, w1);
    wprep<<<dim3( 384/32, 1536/32), dim3(32, 8)>>>(w_fc2,  1536,  384, w2);

    const int MT = NTOK / 128;   // 784

    // 1) LN1 + roll + window partition -> act
    ln_kernel<true><<<NTOK / 8, 256>>>(x, ln1_g, ln1_b, act);
    // 2) QKV
    gemm_mma<0><<<dim3(1152/128, MT), 256, SMEM_DYN>>>(act, wq, b_qkv, qkv, nullptr, nullptr, NC_A, 1152);
    // 3) attention -> act
    attn_kernel<<<dim3(NTOK / WN, 12), 64>>>(qkv, act);
    // 4) proj + reverse/roll + residual
    gemm_mma<2><<<dim3( 384/128, MT), 256, SMEM_DYN>>>(act, wp, b_proj, xres, nullptr, x, NC_A, 384);
    // 5) LN2 -> act
    ln_kernel<false><<<NTOK / 8, 256>>>(xres, ln2_g, ln2_b, act);
    // 6) FC1 + GELU -> hid
    gemm_mma<1><<<dim3(1536/128, MT), 256, SMEM_DYN>>>(act, w1, b_fc1, nullptr, hid, nullptr, NC_A, 1536);
    // 7) FC2 + residual -> out
    gemm_mma<3><<<dim3( 384/128, MT), 256, SMEM_DYN>>>(hid, w2, b_fc2, out, nullptr, xres, NC_H, 384);
}